// round 1
// baseline (speedup 1.0000x reference)
#include <cuda_runtime.h>
#include <cuda_bf16.h>
#include <math.h>

// WaveletAttention: y = x * sigmoid(relu(mean(dwt2_ll(x)) @ W1^T) @ W2^T)
// Shapes: x [8,256,256,256] f32, W1 [16,256], W2 [256,16].
//
// mean(dwt2_ll(x)) collapses (linearity + separability) to
//   (1/135^2) * sum_{i,j} w[i]*w[j]*x[b,c,i,j]
// with w a fixed length-256 weight vector derived from the db8 dec_lo filter,
// symmetric padding, stride-2 valid correlation with the reversed filter.

#define H 256
#define Wd 256
#define PLANE (H*Wd)          // 65536 floats per (b,c)
#define PLANE4 (PLANE/4)      // 16384 float4
#define NBC (8*256)           // 2048 (b,c) pairs
#define OUTLEN 135            // (256 + 16 - 1) / 2
#define INV_MEAN (1.0f/(135.0f*135.0f))

__device__ float g_y[NBC];    // weighted spatial means
__device__ float g_s[NBC];    // channel scales (sigmoid output)

// pywt db8 dec_lo, 16 taps
__constant__ float c_f[16] = {
    -0.00011747678400228192f, 0.0006754494059985568f, -0.0003917403729959771f,
    -0.00487035299301066f, 0.008746094047015655f, 0.013981027917015516f,
    -0.04408825393106472f, -0.01736930100202211f, 0.128747426620186f,
    0.00047248457399797254f, -0.2840155429624281f, -0.015829105256023893f,
    0.5853546836548691f, 0.6756307362980128f, 0.3128715909144659f,
    0.05441584224308161f
};

// Sum of filter taps that hit padded-array position q:
// y[m] = sum_k xe[2m+15-k] f[k], xe[p] = padded[p+1]  =>  q = 2m+16-k,
// valid when (q+k) even and 16 <= q+k <= 284   (m = (q+k-16)/2 in [0,134]).
__device__ __forceinline__ float wcontrib(int q) {
    float s = 0.f;
#pragma unroll
    for (int k = 0; k < 16; ++k) {
        int qk = q + k;
        bool ok = ((qk & 1) == 0) && (qk >= 16) && (qk <= 284);
        s += ok ? c_f[k] : 0.f;
    }
    return s;
}

// padded index -> original index folding (symmetric pad 15 each side):
// orig i receives q = i+15 (interior), q = 14-i (left reflect, i<=14),
// q = 526-i (right reflect, i>=242). Out-of-range q yields contrib 0.
__device__ __forceinline__ float weight_at(int i) {
    return wcontrib(i + 15) + wcontrib(14 - i) + wcontrib(526 - i);
}

// ---------------------------------------------------------------------------
// Kernel 1: per-(b,c) weighted spatial reduction. One block per plane.
// Reads 2 GB total; pure LDG.128 stream + ~5 FMA / 16B.
// ---------------------------------------------------------------------------
__global__ void __launch_bounds__(256) reduce_kernel(const float* __restrict__ x) {
    __shared__ float sw[256];
    __shared__ float red[8];
    const int t = threadIdx.x;

    sw[t] = weight_at(t);          // recompute the weight vector (cheap, exact)
    __syncthreads();

    const int bc = blockIdx.x;
    const float4* __restrict__ p = (const float4*)x + (size_t)bc * PLANE4;

    // idx = it*256 + t :  column group (idx & 63) is constant per thread
    const int jc = (t & 63) * 4;
    const float w0 = sw[jc + 0], w1 = sw[jc + 1], w2 = sw[jc + 2], w3 = sw[jc + 3];
    const int ibase = t >> 6;      // row = ibase + 4*it  (warp-uniform)

    float acc = 0.f;
#pragma unroll 8
    for (int it = 0; it < 64; ++it) {
        float4 v = p[it * 256 + t];
        float wi = sw[ibase + it * 4];
        acc += wi * (w0 * v.x + w1 * v.y + w2 * v.z + w3 * v.w);
    }

#pragma unroll
    for (int o = 16; o; o >>= 1) acc += __shfl_down_sync(0xffffffffu, acc, o);
    if ((t & 31) == 0) red[t >> 5] = acc;
    __syncthreads();
    if (t < 8) {
        float v = red[t];
#pragma unroll
        for (int o = 4; o; o >>= 1) v += __shfl_down_sync(0xffu, v, o);
        if (t == 0) g_y[bc] = v * INV_MEAN;
    }
}

// ---------------------------------------------------------------------------
// Kernel 2: tiny FC  y[8,256] -> relu(y@W1^T)[8,16] -> sigmoid(h@W2^T)[8,256]
// ---------------------------------------------------------------------------
__global__ void __launch_bounds__(256) fc_kernel(const float* __restrict__ W1,
                                                 const float* __restrict__ W2) {
    __shared__ float sh[128];      // h[b,u], 8*16
    const int t = threadIdx.x;
    if (t < 128) {
        const int b = t >> 4, u = t & 15;
        const float* yb = g_y + b * 256;
        const float* w1 = W1 + u * 256;
        float s = 0.f;
#pragma unroll 8
        for (int c = 0; c < 256; ++c) s += yb[c] * w1[c];
        sh[t] = fmaxf(s, 0.f);
    }
    __syncthreads();
#pragma unroll
    for (int r = 0; r < 8; ++r) {
        const int o = r * 256 + t;
        const int b = o >> 8, c = o & 255;
        float s = 0.f;
#pragma unroll
        for (int u = 0; u < 16; ++u) s += sh[b * 16 + u] * W2[c * 16 + u];
        g_s[o] = 1.f / (1.f + expf(-s));
    }
}

// ---------------------------------------------------------------------------
// Kernel 3: out = x * s[b,c].  grid (16, 2048); 4 float4 per thread.
// ---------------------------------------------------------------------------
__global__ void __launch_bounds__(256) scale_kernel(const float* __restrict__ x,
                                                    float* __restrict__ out) {
    const int bc = blockIdx.y;
    const float s = g_s[bc];
    const float4* __restrict__ px = (const float4*)x + (size_t)bc * PLANE4;
    float4* __restrict__ po = (float4*)out + (size_t)bc * PLANE4;
    const int base = blockIdx.x * 1024 + threadIdx.x;
#pragma unroll
    for (int r = 0; r < 4; ++r) {
        float4 v = px[base + r * 256];
        v.x *= s; v.y *= s; v.z *= s; v.w *= s;
        po[base + r * 256] = v;
    }
}

extern "C" void kernel_launch(void* const* d_in, const int* in_sizes, int n_in,
                              void* d_out, int out_size) {
    const float* x  = (const float*)d_in[0];
    const float* W1 = (const float*)d_in[1];   // [16,256]
    const float* W2 = (const float*)d_in[2];   // [256,16]
    float* out = (float*)d_out;

    reduce_kernel<<<NBC, 256>>>(x);
    fc_kernel<<<1, 256>>>(W1, W2);
    scale_kernel<<<dim3(16, NBC), 256>>>(x, out);
}